// round 15
// baseline (speedup 1.0000x reference)
#include <cuda_runtime.h>
#include <cuda_fp16.h>
#include <cstdint>

#define TPB 256

// ===================== PTX wrappers =====================
__device__ __forceinline__ uint32_t smem_u32(const void* p){
    uint32_t a;
    asm("{ .reg .u64 t; cvta.to.shared.u64 t, %1; cvt.u32.u64 %0, t; }":"=r"(a):"l"(p));
    return a;
}
#define LDSM4(r, a) \
    asm volatile("ldmatrix.sync.aligned.m8n8.x4.shared.b16 {%0,%1,%2,%3}, [%4];" \
        :"=r"((r)[0]),"=r"((r)[1]),"=r"((r)[2]),"=r"((r)[3]):"r"(a))
#define STSM2(a, r0, r1) \
    asm volatile("stmatrix.sync.aligned.m8n8.x2.shared.b16 [%0], {%1,%2};" \
        :: "r"(a), "r"(r0), "r"(r1) : "memory")
#define MMA_F16(c, a, b) \
    asm volatile("mma.sync.aligned.m16n8k16.row.col.f32.f16.f16.f32 " \
        "{%0,%1,%2,%3},{%4,%5,%6,%7},{%8,%9},{%0,%1,%2,%3};" \
        :"+f"((c)[0]),"+f"((c)[1]),"+f"((c)[2]),"+f"((c)[3]) \
        :"r"((a)[0]),"r"((a)[1]),"r"((a)[2]),"r"((a)[3]),"r"((b)[0]),"r"((b)[1]))

__device__ __forceinline__ uint32_t packh(float v0, float v1){
    __half2 H = __floats2half2_rn(v0, v1);
    return *(uint32_t*)&H;
}
__device__ __forceinline__ void swst(uint8_t* plane, int P, int r, int nc, uint32_t v){
    *(uint32_t*)(plane + r*P + ((((nc>>3) ^ (r&7)) << 4) | ((nc<<1) & 15))) = v;
}

// ===================== packed weights =====================
#define W3A4_OFF 278528
#define W3B4_OFF 350208
#define WA1T_OFF 415744
__device__ __align__(128) uint8_t g_wb[448512];

__global__ void prep_kernel(const float* __restrict__ w1a, const float* __restrict__ w1b,
                            const float* __restrict__ w2a, const float* __restrict__ w2b,
                            const float* __restrict__ wa1, const float* __restrict__ wa2,
                            const float* __restrict__ w3a, const float* __restrict__ w3b)
{
    int idx = blockIdx.x * blockDim.x + threadIdx.x;
    if (idx < 34816){
        const float* W[6] = {w1a, w1b, w2a, w2b, wa1, wa2};
        const int   NN[6] = {256, 128, 256, 128, 128, 64};
        const int   KS[6] = {4, 16, 8, 16, 8, 8};
        const int   EO[7] = {0, 4096, 12288, 20480, 28672, 32768, 34816};
        const int   BO[6] = {0, 32768, 98304, 163840, 229376, 262144};
        int l = 0;
        while (idx >= EO[l+1]) l++;
        int e = idx - EO[l];
        int lane = e & 31, qq = e >> 5;
        int s = qq % KS[l], T = qq / KS[l];
        int tg = lane & 3, g = lane >> 2;
        int n = T*8 + g;
        int k0 = s*16 + 2*tg;
        int N = NN[l];
        const float* Wl = W[l];
        __half2 H0 = __floats2half2_rn(Wl[(k0  )*N + n], Wl[(k0+1)*N + n]);
        __half2 H1 = __floats2half2_rn(Wl[(k0+8)*N + n], Wl[(k0+9)*N + n]);
        uint2 o;
        o.x = *(uint32_t*)&H0; o.y = *(uint32_t*)&H1;
        *(uint2*)(g_wb + BO[l] + (size_t)e*8) = o;
        return;
    }
    int e = idx - 34816;
    if (e < 8960){           // w3a quads
        int q = e >> 8, n = e & 255;
        float v[4];
        #pragma unroll
        for (int r = 0; r < 4; r++){
            int i = 4*q + r;
            v[r] = (i < 137) ? w3a[i*256 + n] : 0.f;
        }
        __half2 H0 = __floats2half2_rn(v[0], v[1]);
        __half2 H1 = __floats2half2_rn(v[2], v[3]);
        uint2 o; o.x = *(uint32_t*)&H0; o.y = *(uint32_t*)&H1;
        *(uint2*)(g_wb + W3A4_OFF + (size_t)e*8) = o;
    } else if (e < 8960 + 8192){   // w3b quads
        int e2 = e - 8960;
        int q = e2 >> 7, n = e2 & 127;
        __half2 H0 = __floats2half2_rn(w3b[(4*q  )*128 + n], w3b[(4*q+1)*128 + n]);
        __half2 H1 = __floats2half2_rn(w3b[(4*q+2)*128 + n], w3b[(4*q+3)*128 + n]);
        uint2 o; o.x = *(uint32_t*)&H0; o.y = *(uint32_t*)&H1;
        *(uint2*)(g_wb + W3B4_OFF + (size_t)e2*8) = o;
    } else if (e < 8960 + 8192 + 4096){   // wa1 tail quads
        int e3 = e - 8960 - 8192;
        int q = e3 >> 7, n = e3 & 127;
        __half2 H0 = __floats2half2_rn(wa1[(128+4*q  )*128 + n], wa1[(129+4*q)*128 + n]);
        __half2 H1 = __floats2half2_rn(wa1[(130+4*q)*128 + n], wa1[(131+4*q)*128 + n]);
        uint2 o; o.x = *(uint32_t*)&H0; o.y = *(uint32_t*)&H1;
        *(uint2*)(g_wb + WA1T_OFF + (size_t)e3*8) = o;
    }
}

// ===================== smem layout (per CTA, ~55 KB; aliased scratch) ========
#define OFF_BH   0          // big act: 64 x 512B
#define OFF_MH   32768      // m1/x act: 64 x 256B
#define OFF_F    49152
#define F_B1A   0
#define F_B1B   256
#define F_B2A   384
#define F_B2B   640
#define F_BA2   768
#define F_WA3   832
#define F_VIS   896
#define F_GSP   960       // [2][128]; ALIASED: F_H3 after gsb
#define F_SPART 1216      // [256]; ALIASED: F_JP after softmax
#define F_COEF  1472      // [64]
#define F_GSB   1536      // [128]
#define F_JOINT 1664      // [160] (137..159 zeroed)
#define F_RED   1824      // [16]
#define F_TOT   1840
#define F_H3    F_GSP
#define F_JP    F_SPART
#define SMEM_BYTES (OFF_F + F_TOT*4)   // 56512

// ========== GEMM: M=64, 8 warps 2(M)x4(N), warp tile 32 x NT*8, fp16 ==========
template<int KSTEPS, int NT>
__device__ __forceinline__ void gemm(uint32_t aH, int P,
                                     const uint2* __restrict__ Bf,
                                     int mw, int nw, int lane,
                                     float (&acc)[2][NT][4],
                                     const float* __restrict__ bias)
{
    const int tg2 = (lane & 3) * 2;
    #pragma unroll
    for (int t = 0; t < NT; t++){
        float b0 = 0.f, b1 = 0.f;
        if (bias){
            int c = nw*(NT*8) + t*8 + tg2;
            b0 = bias[c]; b1 = bias[c + 1];
        }
        #pragma unroll
        for (int m = 0; m < 2; m++){
            acc[m][t][0] = b0; acc[m][t][1] = b1;
            acc[m][t][2] = b0; acc[m][t][3] = b1;
        }
    }

    const uint32_t rowoff = (uint32_t)((mw*32 + (lane & 15)) * P);
    const uint32_t chi = (uint32_t)(lane >> 4);
    const uint32_t swr = (uint32_t)(lane & 7);
    const uint2* bp = Bf + (size_t)(nw*NT)*KSTEPS*32 + lane;

    #pragma unroll 2
    for (int s = 0; s < KSTEPS; s++){
        uint32_t co = (((2u*s + chi) ^ swr) << 4);
        uint32_t AH[2][4];
        #pragma unroll
        for (int m = 0; m < 2; m++)
            LDSM4(AH[m], aH + rowoff + (uint32_t)(m*16*P) + co);
        const uint2* bps = bp + (size_t)s*32;
        #pragma unroll
        for (int t = 0; t < NT; t++){
            uint2 bb = __ldg(bps + (size_t)t*KSTEPS*32);
            uint32_t BH[2] = {bb.x, bb.y};
            #pragma unroll
            for (int m = 0; m < 2; m++)
                MMA_F16(acc[m][t], AH[m], BH);
        }
    }
}

__global__ void __launch_bounds__(TPB, 4)
value_net_mma(const float* __restrict__ state,
              const float* __restrict__ b1a, const float* __restrict__ b1b,
              const float* __restrict__ b2a, const float* __restrict__ b2b,
              const float* __restrict__ ba1, const float* __restrict__ ba2,
              const float* __restrict__ wa3, const float* __restrict__ ba3,
              const float* __restrict__ b3a, const float* __restrict__ b3b,
              const float* __restrict__ w3c, const float* __restrict__ b3c,
              float* __restrict__ out)
{
    extern __shared__ __align__(128) uint8_t sm[];
    float* F = (float*)(sm + OFF_F);
    const int tid  = threadIdx.x;
    const int lane = tid & 31;
    const int wid  = tid >> 5;
    const int mw   = wid & 1;
    const int nw   = wid >> 1;
    const int g    = lane >> 2;
    const int tg   = lane & 3;
    const int R0   = mw * 32;
    const int rl   = lane & 15;

    const uint32_t sb = smem_u32(sm);
    const uint32_t BH_ = sb + OFF_BH;
    const uint32_t MH_ = sb + OFF_MH;
    uint8_t* pMH = sm + OFF_MH;

    const uint2* B0 = (const uint2*)(g_wb + 0);
    const uint2* B1 = (const uint2*)(g_wb + 32768);
    const uint2* B2 = (const uint2*)(g_wb + 98304);
    const uint2* B3 = (const uint2*)(g_wb + 163840);
    const uint2* B4 = (const uint2*)(g_wb + 229376);
    const uint2* B5 = (const uint2*)(g_wb + 262144);

    // ---- stage x (64 rows x 64) + scalars ----
    {
        int row = tid >> 2, qd = tid & 3;
        const float* xr = state + (size_t)blockIdx.x*4096 + row*64 + qd*16;
        float xv[16];
        #pragma unroll
        for (int j = 0; j < 4; j++) ((float4*)xv)[j] = __ldg((const float4*)(xr + 4*j));
        #pragma unroll
        for (int j = 0; j < 8; j++){
            int nc = qd*16 + 2*j;
            swst(pMH, 256, row, nc, packh(xv[2*j], xv[2*j+1]));
        }
        if (qd == 3) F[F_VIS + row] = (xv[13] > 0.f) ? 1.f : 0.f;   // col 61
        if (tid == 0){
            #pragma unroll
            for (int i = 0; i < 9; i++) F[F_JOINT + i] = xv[i];
        }
        if (tid >= 137 && tid < 160) F[F_JOINT + tid] = 0.f;
        F[F_B1A + tid] = __ldg(&b1a[tid]);
        F[F_B2A + tid] = __ldg(&b2a[tid]);
        if (tid < 128){ F[F_B1B + tid] = __ldg(&b1b[tid]); F[F_B2B + tid] = __ldg(&b2b[tid]); }
        if (tid < 64){  F[F_BA2 + tid] = __ldg(&ba2[tid]); F[F_WA3 + tid] = __ldg(&wa3[tid]); }
    }
    __syncthreads();

    // ============ L0: h1 = relu(x @ w1a + b1a)  K=64 N=256, two NT=4 passes ====
    #pragma unroll
    for (int p = 0; p < 2; p++){
        float acc[2][4][4];
        gemm<4,4>(MH_, 256, B0 + p*2048, mw, nw, lane, acc, &F[F_B1A + p*128]);
        #pragma unroll
        for (int m = 0; m < 2; m++){
            int rowm = R0 + m*16 + rl;
            uint32_t bH = BH_ + (uint32_t)rowm*512;
            uint32_t swr = (uint32_t)(rowm & 7);
            #pragma unroll
            for (int t = 0; t < 4; t++){
                uint32_t off = (((uint32_t)(p*16 + nw*4 + t) ^ swr) << 4);
                float v0 = fmaxf(acc[m][t][0], 0.f);
                float v1 = fmaxf(acc[m][t][1], 0.f);
                float v2 = fmaxf(acc[m][t][2], 0.f);
                float v3 = fmaxf(acc[m][t][3], 0.f);
                STSM2(bH + off, packh(v0, v1), packh(v2, v3));
            }
        }
    }
    __syncthreads();

    // ============ L1: m1 = relu(h1 @ w1b + b1b)  K=256 N=128 ============
    {
        float acc[2][4][4];
        gemm<16,4>(BH_, 512, B1, mw, nw, lane, acc, &F[F_B1B]);
        float visA[2], visB[2];
        #pragma unroll
        for (int m = 0; m < 2; m++){
            visA[m] = F[F_VIS + R0 + m*16 + g];
            visB[m] = F[F_VIS + R0 + m*16 + g + 8];
        }
        #pragma unroll
        for (int m = 0; m < 2; m++){
            int rowm = R0 + m*16 + rl;
            uint32_t bH = MH_ + (uint32_t)rowm*256;
            uint32_t swr = (uint32_t)(rowm & 7);
            #pragma unroll
            for (int t = 0; t < 4; t++){
                float v0 = fmaxf(acc[m][t][0], 0.f);
                float v1 = fmaxf(acc[m][t][1], 0.f);
                float v2 = fmaxf(acc[m][t][2], 0.f);
                float v3 = fmaxf(acc[m][t][3], 0.f);
                uint32_t off = (((uint32_t)(nw*4 + t) ^ swr) << 4);
                STSM2(bH + off, packh(v0, v1), packh(v2, v3));   // UNMASKED m1
                float g0 = v0*visA[m] + v2*visB[m];
                float g1 = v1*visA[m] + v3*visB[m];
                #pragma unroll
                for (int o = 4; o <= 16; o <<= 1){
                    g0 += __shfl_xor_sync(0xffffffffu, g0, o);
                    g1 += __shfl_xor_sync(0xffffffffu, g1, o);
                }
                if (lane < 4){
                    int c = nw*32 + t*8 + 2*tg;
                    if (m == 0){
                        F[F_GSP + mw*128 + c]     = g0;
                        F[F_GSP + mw*128 + c + 1] = g1;
                    } else {
                        F[F_GSP + mw*128 + c]     += g0;
                        F[F_GSP + mw*128 + c + 1] += g1;
                    }
                }
            }
        }
    }
    __syncthreads();
    // gsb partials via packed wa1 tail (split-K x2, quad loads)
    {
        int n = tid & 127, half = tid >> 7;
        const float* g0p = &F[F_GSP];
        const float* g1p = &F[F_GSP + 128];
        const uint2* Wp = (const uint2*)(g_wb + WA1T_OFF) + half*16*128 + n;
        float a = 0.f;
        #pragma unroll 4
        for (int q = 0; q < 16; q++){
            uint2 w = __ldg(Wp + q*128);
            float2 f0 = __half22float2(*(__half2*)&w.x);
            float2 f1 = __half22float2(*(__half2*)&w.y);
            int j = half*64 + 4*q;
            a += (g0p[j]   + g1p[j]  ) * f0.x + (g0p[j+1] + g1p[j+1]) * f0.y
               + (g0p[j+2] + g1p[j+2]) * f1.x + (g0p[j+3] + g1p[j+3]) * f1.y;
        }
        F[F_SPART + tid] = a;
    }
    __syncthreads();
    if (tid < 128){
        F[F_GSB + tid] = (F[F_SPART + tid] + F[F_SPART + 128 + tid]) * (1.f/64.f)
                       + __ldg(&ba1[tid]);
    }
    __syncthreads();

    // ============ L4: att1 = relu(vis*(m1 @ wa1a) + gsb)  K=128 N=128 ============
    {
        float acc[2][4][4];
        gemm<8,4>(MH_, 256, B4, mw, nw, lane, acc, nullptr);
        float visA[2], visB[2];
        #pragma unroll
        for (int m = 0; m < 2; m++){
            visA[m] = F[F_VIS + R0 + m*16 + g];
            visB[m] = F[F_VIS + R0 + m*16 + g + 8];
        }
        #pragma unroll
        for (int m = 0; m < 2; m++){
            int rowm = R0 + m*16 + rl;
            uint32_t bH = BH_ + (uint32_t)rowm*512;
            uint32_t swr = (uint32_t)(rowm & 7);
            #pragma unroll
            for (int t = 0; t < 4; t++){
                int c = nw*32 + t*8 + 2*tg;
                float g0 = F[F_GSB + c], g1 = F[F_GSB + c + 1];
                float v0 = fmaxf(acc[m][t][0]*visA[m] + g0, 0.f);
                float v1 = fmaxf(acc[m][t][1]*visA[m] + g1, 0.f);
                float v2 = fmaxf(acc[m][t][2]*visB[m] + g0, 0.f);
                float v3 = fmaxf(acc[m][t][3]*visB[m] + g1, 0.f);
                uint32_t off = (((uint32_t)(nw*4 + t) ^ swr) << 4);
                STSM2(bH + off, packh(v0, v1), packh(v2, v3));
            }
        }
    }
    __syncthreads();

    // ============ L5: score partials  K=128 N=64 (ba2 folded) ============
    {
        float acc[2][2][4];
        gemm<8,2>(BH_, 512, B5, mw, nw, lane, acc, &F[F_BA2]);
        float pA[2] = {0,0}, pB[2] = {0,0};
        #pragma unroll
        for (int t = 0; t < 2; t++){
            int c = nw*16 + t*8 + 2*tg;
            float w0 = F[F_WA3 + c], w1 = F[F_WA3 + c + 1];
            #pragma unroll
            for (int m = 0; m < 2; m++){
                pA[m] += fmaxf(acc[m][t][0], 0.f)*w0 + fmaxf(acc[m][t][1], 0.f)*w1;
                pB[m] += fmaxf(acc[m][t][2], 0.f)*w0 + fmaxf(acc[m][t][3], 0.f)*w1;
            }
        }
        #pragma unroll
        for (int m = 0; m < 2; m++){
            #pragma unroll
            for (int o = 1; o <= 2; o <<= 1){
                pA[m] += __shfl_xor_sync(0xffffffffu, pA[m], o);
                pB[m] += __shfl_xor_sync(0xffffffffu, pB[m], o);
            }
        }
        if (tg == 0){
            #pragma unroll
            for (int m = 0; m < 2; m++){
                F[F_SPART + nw*64 + R0 + m*16 + g]     = pA[m];
                F[F_SPART + nw*64 + R0 + m*16 + g + 8] = pB[m];
            }
        }
    }
    __syncthreads();

    // ---- softmax + coefficients + joint init ----
    {
        float e = 0.f;
        if (tid < 64){
            float s = F[F_SPART + tid] + F[F_SPART + 64 + tid]
                    + F[F_SPART + 128 + tid] + F[F_SPART + 192 + tid] + __ldg(&ba3[0]);
            e = (s != 0.f) ? expf(s) : 0.f;
            float t1 = e;
            #pragma unroll
            for (int o = 16; o > 0; o >>= 1) t1 += __shfl_xor_sync(0xffffffffu, t1, o);
            if (lane == 0) F[F_RED + wid] = t1;
        }
        __syncthreads();
        if (tid < 64){
            float ssum = F[F_RED] + F[F_RED + 1];
            float coef = (e / ssum) * F[F_VIS + tid];
            F[F_COEF + tid] = coef;
            float t2 = coef;
            #pragma unroll
            for (int o = 16; o > 0; o >>= 1) t2 += __shfl_xor_sync(0xffffffffu, t2, o);
            if (lane == 0) F[F_RED + 4 + wid] = t2;
        }
        __syncthreads();
        if (tid < 128){
            float csum = F[F_RED + 4] + F[F_RED + 5];
            F[F_JOINT + 9 + tid] = csum * F[F_B2B + tid];
        }
    }
    __syncthreads();

    // ============ L2: h2 = relu(m1 @ w2a + b2a)  K=128 N=256, two NT=4 passes ===
    #pragma unroll
    for (int p = 0; p < 2; p++){
        float acc[2][4][4];
        gemm<8,4>(MH_, 256, B2 + p*4096, mw, nw, lane, acc, &F[F_B2A + p*128]);
        #pragma unroll
        for (int m = 0; m < 2; m++){
            int rowm = R0 + m*16 + rl;
            uint32_t bH = BH_ + (uint32_t)rowm*512;
            uint32_t swr = (uint32_t)(rowm & 7);
            #pragma unroll
            for (int t = 0; t < 4; t++){
                uint32_t off = (((uint32_t)(p*16 + nw*4 + t) ^ swr) << 4);
                float v0 = fmaxf(acc[m][t][0], 0.f);
                float v1 = fmaxf(acc[m][t][1], 0.f);
                float v2 = fmaxf(acc[m][t][2], 0.f);
                float v3 = fmaxf(acc[m][t][3], 0.f);
                STSM2(bH + off, packh(v0, v1), packh(v2, v3));
            }
        }
    }
    __syncthreads();

    // ============ L3: jp[mw] = coef . (h2 @ w2b)  K=256 N=128 ============
    {
        float acc[2][4][4];
        gemm<16,4>(BH_, 512, B3, mw, nw, lane, acc, nullptr);
        float cA[2], cB[2];
        #pragma unroll
        for (int m = 0; m < 2; m++){
            cA[m] = F[F_COEF + R0 + m*16 + g];
            cB[m] = F[F_COEF + R0 + m*16 + g + 8];
        }
        #pragma unroll
        for (int t = 0; t < 4; t++){
            int c = nw*32 + t*8 + 2*tg;
            float w0 = 0.f, w1 = 0.f;
            #pragma unroll
            for (int m = 0; m < 2; m++){
                w0 += cA[m]*acc[m][t][0] + cB[m]*acc[m][t][2];
                w1 += cA[m]*acc[m][t][1] + cB[m]*acc[m][t][3];
            }
            #pragma unroll
            for (int o = 4; o <= 16; o <<= 1){
                w0 += __shfl_xor_sync(0xffffffffu, w0, o);
                w1 += __shfl_xor_sync(0xffffffffu, w1, o);
            }
            if (lane < 4){
                F[F_JP + mw*128 + c]     = w0;
                F[F_JP + mw*128 + c + 1] = w1;
            }
        }
    }
    __syncthreads();
    if (tid < 128){
        F[F_JOINT + 9 + tid] += F[F_JP + tid] + F[F_JP + 128 + tid];
    }
    __syncthreads();

    // ============ final MLP: 137 -> 256 -> 128 -> 1 (fp16 quad weights) ========
    {
        int n = tid;
        float a = __ldg(&b3a[n]);
        const float* J = &F[F_JOINT];
        const uint2* Wp = (const uint2*)(g_wb + W3A4_OFF) + n;
        #pragma unroll 5
        for (int q = 0; q < 35; q++){
            uint2 w = __ldg(Wp + q*256);
            float2 f0 = __half22float2(*(__half2*)&w.x);
            float2 f1 = __half22float2(*(__half2*)&w.y);
            a += J[4*q]*f0.x + J[4*q+1]*f0.y + J[4*q+2]*f1.x + J[4*q+3]*f1.y;
        }
        float h3v = fmaxf(a, 0.f);
        __syncthreads();           // wait: JOINT reads done before H3 (aliases GSP) write? H3 aliases GSP (dead); sync orders JP-alias reuse below
        F[F_H3 + n] = h3v;
    }
    __syncthreads();
    {   // layer 2: 128 outputs, split-K x2 over 256 threads, quad loads
        int n = tid & 127, half = tid >> 7;
        float a = half ? 0.f : __ldg(&b3b[n]);
        const float* H = &F[F_H3 + half*128];
        const uint2* Wp = (const uint2*)(g_wb + W3B4_OFF) + half*32*128 + n;
        #pragma unroll 4
        for (int q = 0; q < 32; q++){
            uint2 w = __ldg(Wp + q*128);
            float2 f0 = __half22float2(*(__half2*)&w.x);
            float2 f1 = __half22float2(*(__half2*)&w.y);
            a += H[4*q]*f0.x + H[4*q+1]*f0.y + H[4*q+2]*f1.x + H[4*q+3]*f1.y;
        }
        F[F_JP + tid] = a;
    }
    __syncthreads();
    if (tid < 128){
        float p = fmaxf(F[F_JP + tid] + F[F_JP + 128 + tid], 0.f) * __ldg(&w3c[tid]);
        #pragma unroll
        for (int o = 16; o > 0; o >>= 1) p += __shfl_xor_sync(0xffffffffu, p, o);
        if (lane == 0) F[F_RED + wid] = p;
    }
    __syncthreads();
    if (tid == 0){
        out[blockIdx.x] = F[F_RED] + F[F_RED + 1] + F[F_RED + 2] + F[F_RED + 3]
                        + __ldg(&b3c[0]);
    }
}

extern "C" void kernel_launch(void* const* d_in, const int* in_sizes, int n_in,
                              void* d_out, int out_size)
{
    (void)in_sizes; (void)n_in; (void)out_size;
    const float* state = (const float*)d_in[0];
    const float* w1a = (const float*)d_in[1];  const float* b1a = (const float*)d_in[2];
    const float* w1b = (const float*)d_in[3];  const float* b1b = (const float*)d_in[4];
    const float* w2a = (const float*)d_in[5];  const float* b2a = (const float*)d_in[6];
    const float* w2b = (const float*)d_in[7];  const float* b2b = (const float*)d_in[8];
    const float* wa1 = (const float*)d_in[9];  const float* ba1 = (const float*)d_in[10];
    const float* wa2 = (const float*)d_in[11]; const float* ba2 = (const float*)d_in[12];
    const float* wa3 = (const float*)d_in[13]; const float* ba3 = (const float*)d_in[14];
    const float* w3a = (const float*)d_in[15]; const float* b3a = (const float*)d_in[16];
    const float* w3b = (const float*)d_in[17]; const float* b3b = (const float*)d_in[18];
    const float* w3c = (const float*)d_in[19]; const float* b3c = (const float*)d_in[20];
    float* out = (float*)d_out;

    prep_kernel<<<(56064 + 255)/256, 256>>>(w1a, w1b, w2a, w2b, wa1, wa2, w3a, w3b);

    cudaFuncSetAttribute(value_net_mma,
                         cudaFuncAttributeMaxDynamicSharedMemorySize, SMEM_BYTES);
    value_net_mma<<<4096, TPB, SMEM_BYTES>>>(
        state, b1a, b1b, b2a, b2b, ba1, ba2, wa3, ba3,
        b3a, b3b, w3c, b3c, out);
}

// round 16
// speedup vs baseline: 1.1025x; 1.1025x over previous
#include <cuda_runtime.h>
#include <cuda_fp16.h>
#include <cstdint>

#define TPB 256

// ===================== PTX wrappers =====================
__device__ __forceinline__ uint32_t smem_u32(const void* p){
    uint32_t a;
    asm("{ .reg .u64 t; cvta.to.shared.u64 t, %1; cvt.u32.u64 %0, t; }":"=r"(a):"l"(p));
    return a;
}
#define LDSM4(r, a) \
    asm volatile("ldmatrix.sync.aligned.m8n8.x4.shared.b16 {%0,%1,%2,%3}, [%4];" \
        :"=r"((r)[0]),"=r"((r)[1]),"=r"((r)[2]),"=r"((r)[3]):"r"(a))
#define STSM2(a, r0, r1) \
    asm volatile("stmatrix.sync.aligned.m8n8.x2.shared.b16 [%0], {%1,%2};" \
        :: "r"(a), "r"(r0), "r"(r1) : "memory")
#define MMA_F16(c, a, b) \
    asm volatile("mma.sync.aligned.m16n8k16.row.col.f32.f16.f16.f32 " \
        "{%0,%1,%2,%3},{%4,%5,%6,%7},{%8,%9},{%0,%1,%2,%3};" \
        :"+f"((c)[0]),"+f"((c)[1]),"+f"((c)[2]),"+f"((c)[3]) \
        :"r"((a)[0]),"r"((a)[1]),"r"((a)[2]),"r"((a)[3]),"r"((b)[0]),"r"((b)[1]))

__device__ __forceinline__ uint32_t packh(float v0, float v1){
    __half2 H = __floats2half2_rn(v0, v1);
    return *(uint32_t*)&H;
}
__device__ __forceinline__ void pack2(float v0, float v1, uint32_t& hi, uint32_t& lo){
    __half h0 = __float2half_rn(v0), h1 = __float2half_rn(v1);
    __half2 H; H.x = h0; H.y = h1;
    hi = *(uint32_t*)&H;
    __half2 L = __floats2half2_rn(v0 - __half2float(h0), v1 - __half2float(h1));
    lo = *(uint32_t*)&L;
}
__device__ __forceinline__ void swst(uint8_t* plane, int P, int r, int nc, uint32_t v){
    *(uint32_t*)(plane + r*P + ((((nc>>3) ^ (r&7)) << 4) | ((nc<<1) & 15))) = v;
}

// ===================== packed weights =====================
// [0, 278528): MMA fragments for L0..L5
// WA1T: wa1 tail rows 128..255 quad-packed (32 x 128 uint2)
// W3AF: w3a MMA fragments (K=144 padded, N=256)
// W3BF: w3b MMA fragments (K=256, N=128)
#define WA1T_OFF 278528
#define W3AF_OFF 311296
#define W3BF_OFF 385024
__device__ __align__(128) uint8_t g_wb[450560];
__device__ float g_joint[4096 * 144];

__global__ void prep_kernel(const float* __restrict__ w1a, const float* __restrict__ w1b,
                            const float* __restrict__ w2a, const float* __restrict__ w2b,
                            const float* __restrict__ wa1, const float* __restrict__ wa2,
                            const float* __restrict__ w3a, const float* __restrict__ w3b)
{
    int idx = blockIdx.x * blockDim.x + threadIdx.x;
    if (idx < 34816){
        const float* W[6] = {w1a, w1b, w2a, w2b, wa1, wa2};
        const int   NN[6] = {256, 128, 256, 128, 128, 64};
        const int   KS[6] = {4, 16, 8, 16, 8, 8};
        const int   EO[7] = {0, 4096, 12288, 20480, 28672, 32768, 34816};
        const int   BO[6] = {0, 32768, 98304, 163840, 229376, 262144};
        int l = 0;
        while (idx >= EO[l+1]) l++;
        int e = idx - EO[l];
        int lane = e & 31, qq = e >> 5;
        int s = qq % KS[l], T = qq / KS[l];
        int tg = lane & 3, g = lane >> 2;
        int n = T*8 + g;
        int k0 = s*16 + 2*tg;
        int N = NN[l];
        const float* Wl = W[l];
        __half2 H0 = __floats2half2_rn(Wl[(k0  )*N + n], Wl[(k0+1)*N + n]);
        __half2 H1 = __floats2half2_rn(Wl[(k0+8)*N + n], Wl[(k0+9)*N + n]);
        uint2 o;
        o.x = *(uint32_t*)&H0; o.y = *(uint32_t*)&H1;
        *(uint2*)(g_wb + BO[l] + (size_t)e*8) = o;
        return;
    }
    int e = idx - 34816;
    if (e < 4096){           // wa1 tail quads
        int q = e >> 7, n = e & 127;
        __half2 H0 = __floats2half2_rn(wa1[(128+4*q  )*128 + n], wa1[(129+4*q)*128 + n]);
        __half2 H1 = __floats2half2_rn(wa1[(130+4*q)*128 + n], wa1[(131+4*q)*128 + n]);
        uint2 o; o.x = *(uint32_t*)&H0; o.y = *(uint32_t*)&H1;
        *(uint2*)(g_wb + WA1T_OFF + (size_t)e*8) = o;
        return;
    }
    int e2 = e - 4096;
    if (e2 < 9216){          // w3a fragments: K=144 (pad >=137 zero), N=256, KS=9
        int lane = e2 & 31, qq = e2 >> 5;
        int s = qq % 9, T = qq / 9;
        int tg = lane & 3, g = lane >> 2;
        int n = T*8 + g;
        int k0 = s*16 + 2*tg;
        float v0 = (k0   < 137) ? w3a[(k0  )*256 + n] : 0.f;
        float v1 = (k0+1 < 137) ? w3a[(k0+1)*256 + n] : 0.f;
        float v2 = (k0+8 < 137) ? w3a[(k0+8)*256 + n] : 0.f;
        float v3 = (k0+9 < 137) ? w3a[(k0+9)*256 + n] : 0.f;
        __half2 H0 = __floats2half2_rn(v0, v1);
        __half2 H1 = __floats2half2_rn(v2, v3);
        uint2 o; o.x = *(uint32_t*)&H0; o.y = *(uint32_t*)&H1;
        *(uint2*)(g_wb + W3AF_OFF + (size_t)e2*8) = o;
        return;
    }
    int e3 = e2 - 9216;
    if (e3 < 8192){          // w3b fragments: K=256, N=128, KS=16
        int lane = e3 & 31, qq = e3 >> 5;
        int s = qq % 16, T = qq / 16;
        int tg = lane & 3, g = lane >> 2;
        int n = T*8 + g;
        int k0 = s*16 + 2*tg;
        __half2 H0 = __floats2half2_rn(w3b[(k0  )*128 + n], w3b[(k0+1)*128 + n]);
        __half2 H1 = __floats2half2_rn(w3b[(k0+8)*128 + n], w3b[(k0+9)*128 + n]);
        uint2 o; o.x = *(uint32_t*)&H0; o.y = *(uint32_t*)&H1;
        *(uint2*)(g_wb + W3BF_OFF + (size_t)e3*8) = o;
    }
}

// ===================== main kernel smem layout (per CTA) =====================
#define OFF_BH   0          // big act: 64 x 512B
#define OFF_MH   32768      // m1/x act: 64 x 256B
#define OFF_F    49152
#define F_B1A   0
#define F_B1B   256
#define F_B2A   384
#define F_B2B   640
#define F_BA2   768
#define F_WA3   832
#define F_VIS   896
#define F_GSP   960       // [2][128]
#define F_SPART 1216      // [256]; aliased as F_JP after softmax
#define F_COEF  1472
#define F_GSB   1536
#define F_JOINT 1664      // [160] (137..159 zeroed)
#define F_RED   1824
#define F_TOT   1840
#define F_JP    F_SPART
#define SMEM_BYTES (OFF_F + F_TOT*4)   // 56512

// ========== single-term fp16 GEMM (main kernel) ==========
template<int KSTEPS, int NT>
__device__ __forceinline__ void gemm(uint32_t aH, int P,
                                     const uint2* __restrict__ Bf,
                                     int mw, int nw, int lane,
                                     float (&acc)[2][NT][4],
                                     const float* __restrict__ bias)
{
    const int tg2 = (lane & 3) * 2;
    #pragma unroll
    for (int t = 0; t < NT; t++){
        float b0 = 0.f, b1 = 0.f;
        if (bias){
            int c = nw*(NT*8) + t*8 + tg2;
            b0 = bias[c]; b1 = bias[c + 1];
        }
        #pragma unroll
        for (int m = 0; m < 2; m++){
            acc[m][t][0] = b0; acc[m][t][1] = b1;
            acc[m][t][2] = b0; acc[m][t][3] = b1;
        }
    }
    const uint32_t rowoff = (uint32_t)((mw*32 + (lane & 15)) * P);
    const uint32_t chi = (uint32_t)(lane >> 4);
    const uint32_t swr = (uint32_t)(lane & 7);
    const uint2* bp = Bf + (size_t)(nw*NT)*KSTEPS*32 + lane;
    #pragma unroll 2
    for (int s = 0; s < KSTEPS; s++){
        uint32_t co = (((2u*s + chi) ^ swr) << 4);
        uint32_t AH[2][4];
        #pragma unroll
        for (int m = 0; m < 2; m++)
            LDSM4(AH[m], aH + rowoff + (uint32_t)(m*16*P) + co);
        const uint2* bps = bp + (size_t)s*32;
        #pragma unroll
        for (int t = 0; t < NT; t++){
            uint2 bb = __ldg(bps + (size_t)t*KSTEPS*32);
            uint32_t BH[2] = {bb.x, bb.y};
            #pragma unroll
            for (int m = 0; m < 2; m++)
                MMA_F16(acc[m][t], AH[m], BH);
        }
    }
}

// ========== 2-term fp16 GEMM (tail kernel; A hi+lo planes) ==========
template<int KSTEPS, int NT>
__device__ __forceinline__ void gemm2(uint32_t aH, uint32_t aL, int P,
                                      const uint2* __restrict__ Bf,
                                      int mw, int nw, int lane,
                                      float (&acc)[2][NT][4],
                                      const float* __restrict__ bias)
{
    const int tg2 = (lane & 3) * 2;
    #pragma unroll
    for (int t = 0; t < NT; t++){
        int c = nw*(NT*8) + t*8 + tg2;
        float b0 = __ldg(&bias[c]), b1 = __ldg(&bias[c + 1]);
        #pragma unroll
        for (int m = 0; m < 2; m++){
            acc[m][t][0] = b0; acc[m][t][1] = b1;
            acc[m][t][2] = b0; acc[m][t][3] = b1;
        }
    }
    const uint32_t rowoff = (uint32_t)((mw*32 + (lane & 15)) * P);
    const uint32_t chi = (uint32_t)(lane >> 4);
    const uint32_t swr = (uint32_t)(lane & 7);
    const uint2* bp = Bf + (size_t)(nw*NT)*KSTEPS*32 + lane;
    #pragma unroll 2
    for (int s = 0; s < KSTEPS; s++){
        uint32_t co = (((2u*s + chi) ^ swr) << 4);
        uint32_t AH[2][4], AL[2][4];
        #pragma unroll
        for (int m = 0; m < 2; m++){
            LDSM4(AH[m], aH + rowoff + (uint32_t)(m*16*P) + co);
            LDSM4(AL[m], aL + rowoff + (uint32_t)(m*16*P) + co);
        }
        const uint2* bps = bp + (size_t)s*32;
        #pragma unroll
        for (int t = 0; t < NT; t++){
            uint2 bb = __ldg(bps + (size_t)t*KSTEPS*32);
            uint32_t BH[2] = {bb.x, bb.y};
            #pragma unroll
            for (int m = 0; m < 2; m++){
                MMA_F16(acc[m][t], AH[m], BH);
                MMA_F16(acc[m][t], AL[m], BH);
            }
        }
    }
}

__global__ void __launch_bounds__(TPB, 4)
value_net_mma(const float* __restrict__ state,
              const float* __restrict__ b1a, const float* __restrict__ b1b,
              const float* __restrict__ b2a, const float* __restrict__ b2b,
              const float* __restrict__ ba1, const float* __restrict__ ba2,
              const float* __restrict__ wa3, const float* __restrict__ ba3)
{
    extern __shared__ __align__(128) uint8_t sm[];
    float* F = (float*)(sm + OFF_F);
    const int tid  = threadIdx.x;
    const int lane = tid & 31;
    const int wid  = tid >> 5;
    const int mw   = wid & 1;
    const int nw   = wid >> 1;
    const int g    = lane >> 2;
    const int tg   = lane & 3;
    const int R0   = mw * 32;
    const int rl   = lane & 15;

    const uint32_t sb = smem_u32(sm);
    const uint32_t BH_ = sb + OFF_BH;
    const uint32_t MH_ = sb + OFF_MH;
    uint8_t* pMH = sm + OFF_MH;

    const uint2* B0 = (const uint2*)(g_wb + 0);
    const uint2* B1 = (const uint2*)(g_wb + 32768);
    const uint2* B2 = (const uint2*)(g_wb + 98304);
    const uint2* B3 = (const uint2*)(g_wb + 163840);
    const uint2* B4 = (const uint2*)(g_wb + 229376);
    const uint2* B5 = (const uint2*)(g_wb + 262144);

    // ---- stage x + scalars ----
    {
        int row = tid >> 2, qd = tid & 3;
        const float* xr = state + (size_t)blockIdx.x*4096 + row*64 + qd*16;
        float xv[16];
        #pragma unroll
        for (int j = 0; j < 4; j++) ((float4*)xv)[j] = __ldg((const float4*)(xr + 4*j));
        #pragma unroll
        for (int j = 0; j < 8; j++){
            int nc = qd*16 + 2*j;
            swst(pMH, 256, row, nc, packh(xv[2*j], xv[2*j+1]));
        }
        if (qd == 3) F[F_VIS + row] = (xv[13] > 0.f) ? 1.f : 0.f;   // col 61
        if (tid == 0){
            #pragma unroll
            for (int i = 0; i < 9; i++) F[F_JOINT + i] = xv[i];
        }
        if (tid >= 137 && tid < 160) F[F_JOINT + tid] = 0.f;
        F[F_B1A + tid] = __ldg(&b1a[tid]);
        F[F_B2A + tid] = __ldg(&b2a[tid]);
        if (tid < 128){ F[F_B1B + tid] = __ldg(&b1b[tid]); F[F_B2B + tid] = __ldg(&b2b[tid]); }
        if (tid < 64){  F[F_BA2 + tid] = __ldg(&ba2[tid]); F[F_WA3 + tid] = __ldg(&wa3[tid]); }
    }
    __syncthreads();

    // ============ L0: h1 = relu(x @ w1a + b1a)  K=64 N=256, two NT=4 passes ====
    #pragma unroll
    for (int p = 0; p < 2; p++){
        float acc[2][4][4];
        gemm<4,4>(MH_, 256, B0 + p*2048, mw, nw, lane, acc, &F[F_B1A + p*128]);
        #pragma unroll
        for (int m = 0; m < 2; m++){
            int rowm = R0 + m*16 + rl;
            uint32_t bH = BH_ + (uint32_t)rowm*512;
            uint32_t swr = (uint32_t)(rowm & 7);
            #pragma unroll
            for (int t = 0; t < 4; t++){
                uint32_t off = (((uint32_t)(p*16 + nw*4 + t) ^ swr) << 4);
                float v0 = fmaxf(acc[m][t][0], 0.f);
                float v1 = fmaxf(acc[m][t][1], 0.f);
                float v2 = fmaxf(acc[m][t][2], 0.f);
                float v3 = fmaxf(acc[m][t][3], 0.f);
                STSM2(bH + off, packh(v0, v1), packh(v2, v3));
            }
        }
    }
    __syncthreads();

    // ============ L1: m1 = relu(h1 @ w1b + b1b)  K=256 N=128 ============
    {
        float acc[2][4][4];
        gemm<16,4>(BH_, 512, B1, mw, nw, lane, acc, &F[F_B1B]);
        float visA[2], visB[2];
        #pragma unroll
        for (int m = 0; m < 2; m++){
            visA[m] = F[F_VIS + R0 + m*16 + g];
            visB[m] = F[F_VIS + R0 + m*16 + g + 8];
        }
        #pragma unroll
        for (int m = 0; m < 2; m++){
            int rowm = R0 + m*16 + rl;
            uint32_t bH = MH_ + (uint32_t)rowm*256;
            uint32_t swr = (uint32_t)(rowm & 7);
            #pragma unroll
            for (int t = 0; t < 4; t++){
                float v0 = fmaxf(acc[m][t][0], 0.f);
                float v1 = fmaxf(acc[m][t][1], 0.f);
                float v2 = fmaxf(acc[m][t][2], 0.f);
                float v3 = fmaxf(acc[m][t][3], 0.f);
                uint32_t off = (((uint32_t)(nw*4 + t) ^ swr) << 4);
                STSM2(bH + off, packh(v0, v1), packh(v2, v3));   // UNMASKED m1
                float g0 = v0*visA[m] + v2*visB[m];
                float g1 = v1*visA[m] + v3*visB[m];
                #pragma unroll
                for (int o = 4; o <= 16; o <<= 1){
                    g0 += __shfl_xor_sync(0xffffffffu, g0, o);
                    g1 += __shfl_xor_sync(0xffffffffu, g1, o);
                }
                if (lane < 4){
                    int c = nw*32 + t*8 + 2*tg;
                    if (m == 0){
                        F[F_GSP + mw*128 + c]     = g0;
                        F[F_GSP + mw*128 + c + 1] = g1;
                    } else {
                        F[F_GSP + mw*128 + c]     += g0;
                        F[F_GSP + mw*128 + c + 1] += g1;
                    }
                }
            }
        }
    }
    __syncthreads();
    // gsb partials via packed wa1 tail (split-K x2, quad loads)
    {
        int n = tid & 127, half = tid >> 7;
        const float* g0p = &F[F_GSP];
        const float* g1p = &F[F_GSP + 128];
        const uint2* Wp = (const uint2*)(g_wb + WA1T_OFF) + half*16*128 + n;
        float a = 0.f;
        #pragma unroll 4
        for (int q = 0; q < 16; q++){
            uint2 w = __ldg(Wp + q*128);
            float2 f0 = __half22float2(*(__half2*)&w.x);
            float2 f1 = __half22float2(*(__half2*)&w.y);
            int j = half*64 + 4*q;
            a += (g0p[j]   + g1p[j]  ) * f0.x + (g0p[j+1] + g1p[j+1]) * f0.y
               + (g0p[j+2] + g1p[j+2]) * f1.x + (g0p[j+3] + g1p[j+3]) * f1.y;
        }
        F[F_SPART + tid] = a;
    }
    __syncthreads();
    if (tid < 128){
        F[F_GSB + tid] = (F[F_SPART + tid] + F[F_SPART + 128 + tid]) * (1.f/64.f)
                       + __ldg(&ba1[tid]);
    }
    __syncthreads();

    // ============ L4: att1 = relu(vis*(m1 @ wa1a) + gsb)  K=128 N=128 ============
    {
        float acc[2][4][4];
        gemm<8,4>(MH_, 256, B4, mw, nw, lane, acc, nullptr);
        float visA[2], visB[2];
        #pragma unroll
        for (int m = 0; m < 2; m++){
            visA[m] = F[F_VIS + R0 + m*16 + g];
            visB[m] = F[F_VIS + R0 + m*16 + g + 8];
        }
        #pragma unroll
        for (int m = 0; m < 2; m++){
            int rowm = R0 + m*16 + rl;
            uint32_t bH = BH_ + (uint32_t)rowm*512;
            uint32_t swr = (uint32_t)(rowm & 7);
            #pragma unroll
            for (int t = 0; t < 4; t++){
                int c = nw*32 + t*8 + 2*tg;
                float g0 = F[F_GSB + c], g1 = F[F_GSB + c + 1];
                float v0 = fmaxf(acc[m][t][0]*visA[m] + g0, 0.f);
                float v1 = fmaxf(acc[m][t][1]*visA[m] + g1, 0.f);
                float v2 = fmaxf(acc[m][t][2]*visB[m] + g0, 0.f);
                float v3 = fmaxf(acc[m][t][3]*visB[m] + g1, 0.f);
                uint32_t off = (((uint32_t)(nw*4 + t) ^ swr) << 4);
                STSM2(bH + off, packh(v0, v1), packh(v2, v3));
            }
        }
    }
    __syncthreads();

    // ============ L5: score partials  K=128 N=64 (ba2 folded) ============
    {
        float acc[2][2][4];
        gemm<8,2>(BH_, 512, B5, mw, nw, lane, acc, &F[F_BA2]);
        float pA[2] = {0,0}, pB[2] = {0,0};
        #pragma unroll
        for (int t = 0; t < 2; t++){
            int c = nw*16 + t*8 + 2*tg;
            float w0 = F[F_WA3 + c], w1 = F[F_WA3 + c + 1];
            #pragma unroll
            for (int m = 0; m < 2; m++){
                pA[m] += fmaxf(acc[m][t][0], 0.f)*w0 + fmaxf(acc[m][t][1], 0.f)*w1;
                pB[m] += fmaxf(acc[m][t][2], 0.f)*w0 + fmaxf(acc[m][t][3], 0.f)*w1;
            }
        }
        #pragma unroll
        for (int m = 0; m < 2; m++){
            #pragma unroll
            for (int o = 1; o <= 2; o <<= 1){
                pA[m] += __shfl_xor_sync(0xffffffffu, pA[m], o);
                pB[m] += __shfl_xor_sync(0xffffffffu, pB[m], o);
            }
        }
        if (tg == 0){
            #pragma unroll
            for (int m = 0; m < 2; m++){
                F[F_SPART + nw*64 + R0 + m*16 + g]     = pA[m];
                F[F_SPART + nw*64 + R0 + m*16 + g + 8] = pB[m];
            }
        }
    }
    __syncthreads();

    // ---- softmax + coefficients + joint init ----
    {
        float e = 0.f;
        if (tid < 64){
            float s = F[F_SPART + tid] + F[F_SPART + 64 + tid]
                    + F[F_SPART + 128 + tid] + F[F_SPART + 192 + tid] + __ldg(&ba3[0]);
            e = (s != 0.f) ? expf(s) : 0.f;
            float t1 = e;
            #pragma unroll
            for (int o = 16; o > 0; o >>= 1) t1 += __shfl_xor_sync(0xffffffffu, t1, o);
            if (lane == 0) F[F_RED + wid] = t1;
        }
        __syncthreads();
        if (tid < 64){
            float ssum = F[F_RED] + F[F_RED + 1];
            float coef = (e / ssum) * F[F_VIS + tid];
            F[F_COEF + tid] = coef;
            float t2 = coef;
            #pragma unroll
            for (int o = 16; o > 0; o >>= 1) t2 += __shfl_xor_sync(0xffffffffu, t2, o);
            if (lane == 0) F[F_RED + 4 + wid] = t2;
        }
        __syncthreads();
        if (tid < 128){
            float csum = F[F_RED + 4] + F[F_RED + 5];
            F[F_JOINT + 9 + tid] = csum * F[F_B2B + tid];
        }
    }
    __syncthreads();

    // ============ L2: h2 = relu(m1 @ w2a + b2a)  K=128 N=256, two NT=4 passes ===
    #pragma unroll
    for (int p = 0; p < 2; p++){
        float acc[2][4][4];
        gemm<8,4>(MH_, 256, B2 + p*4096, mw, nw, lane, acc, &F[F_B2A + p*128]);
        #pragma unroll
        for (int m = 0; m < 2; m++){
            int rowm = R0 + m*16 + rl;
            uint32_t bH = BH_ + (uint32_t)rowm*512;
            uint32_t swr = (uint32_t)(rowm & 7);
            #pragma unroll
            for (int t = 0; t < 4; t++){
                uint32_t off = (((uint32_t)(p*16 + nw*4 + t) ^ swr) << 4);
                float v0 = fmaxf(acc[m][t][0], 0.f);
                float v1 = fmaxf(acc[m][t][1], 0.f);
                float v2 = fmaxf(acc[m][t][2], 0.f);
                float v3 = fmaxf(acc[m][t][3], 0.f);
                STSM2(bH + off, packh(v0, v1), packh(v2, v3));
            }
        }
    }
    __syncthreads();

    // ============ L3: jp[mw] = coef . (h2 @ w2b)  K=256 N=128 ============
    {
        float acc[2][4][4];
        gemm<16,4>(BH_, 512, B3, mw, nw, lane, acc, nullptr);
        float cA[2], cB[2];
        #pragma unroll
        for (int m = 0; m < 2; m++){
            cA[m] = F[F_COEF + R0 + m*16 + g];
            cB[m] = F[F_COEF + R0 + m*16 + g + 8];
        }
        #pragma unroll
        for (int t = 0; t < 4; t++){
            int c = nw*32 + t*8 + 2*tg;
            float w0 = 0.f, w1 = 0.f;
            #pragma unroll
            for (int m = 0; m < 2; m++){
                w0 += cA[m]*acc[m][t][0] + cB[m]*acc[m][t][2];
                w1 += cA[m]*acc[m][t][1] + cB[m]*acc[m][t][3];
            }
            #pragma unroll
            for (int o = 4; o <= 16; o <<= 1){
                w0 += __shfl_xor_sync(0xffffffffu, w0, o);
                w1 += __shfl_xor_sync(0xffffffffu, w1, o);
            }
            if (lane < 4){
                F[F_JP + mw*128 + c]     = w0;
                F[F_JP + mw*128 + c + 1] = w1;
            }
        }
    }
    __syncthreads();
    if (tid < 128){
        F[F_JOINT + 9 + tid] += F[F_JP + tid] + F[F_JP + 128 + tid];
    }
    __syncthreads();
    if (tid < 144) g_joint[(size_t)blockIdx.x*144 + tid] = F[F_JOINT + tid];
}

// ===================== tail kernel: batched final MLP =====================
#define TOFF_AH  0          // joint hi: 64 x 384B
#define TOFF_AL  24576
#define TOFF_H3H 49152      // h3 hi: 64 x 512B
#define TOFF_H3L 81920
#define TOFF_F   114688
#define TSMEM_BYTES (TOFF_F + 272*4)

__global__ void __launch_bounds__(TPB)
value_net_tail(const float* __restrict__ b3a, const float* __restrict__ b3b,
               const float* __restrict__ w3c, const float* __restrict__ b3c,
               float* __restrict__ out)
{
    extern __shared__ __align__(128) uint8_t sm[];
    float* F = (float*)(sm + TOFF_F);
    const int tid  = threadIdx.x;
    const int lane = tid & 31;
    const int wid  = tid >> 5;
    const int mw   = wid & 1;
    const int nw   = wid >> 1;
    const int g    = lane >> 2;
    const int tg   = lane & 3;
    const int R0   = mw * 32;
    const int rl   = lane & 15;

    const uint32_t sb = smem_u32(sm);
    const uint32_t AH_ = sb + TOFF_AH, AL_ = sb + TOFF_AL;
    const uint32_t H3H_ = sb + TOFF_H3H, H3L_ = sb + TOFF_H3L;
    uint8_t* pAH = sm + TOFF_AH; uint8_t* pAL = sm + TOFF_AL;

    const uint2* BA = (const uint2*)(g_wb + W3AF_OFF);
    const uint2* BB = (const uint2*)(g_wb + W3BF_OFF);

    // ---- stage joint (64 rows x 144) ----
    {
        int row = tid >> 2, qd = tid & 3;
        const float* jp = g_joint + (size_t)(blockIdx.x*64 + row)*144 + qd*36;
        float jv[36];
        #pragma unroll
        for (int j = 0; j < 9; j++) ((float4*)jv)[j] = *(const float4*)(jp + 4*j);
        #pragma unroll
        for (int j = 0; j < 18; j++){
            int nc = qd*36 + 2*j;
            uint32_t h, l;
            pack2(jv[2*j], jv[2*j+1], h, l);
            swst(pAH, 384, row, nc, h);
            swst(pAL, 384, row, nc, l);
        }
    }
    __syncthreads();

    // ---- T1: h3 = relu(joint @ w3a + b3a)  K=144 N=256 ----
    {
        float acc[2][8][4];
        gemm2<9,8>(AH_, AL_, 384, BA, mw, nw, lane, acc, b3a);
        #pragma unroll
        for (int m = 0; m < 2; m++){
            int rowm = R0 + m*16 + rl;
            uint32_t bH = H3H_ + (uint32_t)rowm*512;
            uint32_t bL = H3L_ + (uint32_t)rowm*512;
            uint32_t swr = (uint32_t)(rowm & 7);
            #pragma unroll
            for (int t = 0; t < 8; t++){
                uint32_t off = (((uint32_t)(nw*8 + t) ^ swr) << 4);
                float v0 = fmaxf(acc[m][t][0], 0.f);
                float v1 = fmaxf(acc[m][t][1], 0.f);
                float v2 = fmaxf(acc[m][t][2], 0.f);
                float v3 = fmaxf(acc[m][t][3], 0.f);
                uint32_t h01, l01, h23, l23;
                pack2(v0, v1, h01, l01);
                pack2(v2, v3, h23, l23);
                STSM2(bH + off, h01, h23);
                STSM2(bL + off, l01, l23);
            }
        }
    }
    __syncthreads();

    // ---- T2: value partials = relu(h3 @ w3b + b3b) . w3c  K=256 N=128 ----
    {
        float acc[2][4][4];
        gemm2<16,4>(H3H_, H3L_, 512, BB, mw, nw, lane, acc, b3b);
        float pA[2] = {0,0}, pB[2] = {0,0};
        #pragma unroll
        for (int t = 0; t < 4; t++){
            int c = nw*32 + t*8 + 2*tg;
            float w0 = __ldg(&w3c[c]), w1 = __ldg(&w3c[c + 1]);
            #pragma unroll
            for (int m = 0; m < 2; m++){
                pA[m] += fmaxf(acc[m][t][0], 0.f)*w0 + fmaxf(acc[m][t][1], 0.f)*w1;
                pB[m] += fmaxf(acc[m][t][2], 0.f)*w0 + fmaxf(acc[m][t][3], 0.f)*w1;
            }
        }
        #pragma unroll
        for (int m = 0; m < 2; m++){
            #pragma unroll
            for (int o = 1; o <= 2; o <<= 1){
                pA[m] += __shfl_xor_sync(0xffffffffu, pA[m], o);
                pB[m] += __shfl_xor_sync(0xffffffffu, pB[m], o);
            }
        }
        if (tg == 0){
            #pragma unroll
            for (int m = 0; m < 2; m++){
                F[nw*64 + R0 + m*16 + g]     = pA[m];
                F[nw*64 + R0 + m*16 + g + 8] = pB[m];
            }
        }
    }
    __syncthreads();
    if (tid < 64){
        out[blockIdx.x*64 + tid] = F[tid] + F[64 + tid] + F[128 + tid] + F[192 + tid]
                                 + __ldg(&b3c[0]);
    }
}

extern "C" void kernel_launch(void* const* d_in, const int* in_sizes, int n_in,
                              void* d_out, int out_size)
{
    (void)in_sizes; (void)n_in; (void)out_size;
    const float* state = (const float*)d_in[0];
    const float* w1a = (const float*)d_in[1];  const float* b1a = (const float*)d_in[2];
    const float* w1b = (const float*)d_in[3];  const float* b1b = (const float*)d_in[4];
    const float* w2a = (const float*)d_in[5];  const float* b2a = (const float*)d_in[6];
    const float* w2b = (const float*)d_in[7];  const float* b2b = (const float*)d_in[8];
    const float* wa1 = (const float*)d_in[9];  const float* ba1 = (const float*)d_in[10];
    const float* wa2 = (const float*)d_in[11]; const float* ba2 = (const float*)d_in[12];
    const float* wa3 = (const float*)d_in[13]; const float* ba3 = (const float*)d_in[14];
    const float* w3a = (const float*)d_in[15]; const float* b3a = (const float*)d_in[16];
    const float* w3b = (const float*)d_in[17]; const float* b3b = (const float*)d_in[18];
    const float* w3c = (const float*)d_in[19]; const float* b3c = (const float*)d_in[20];
    float* out = (float*)d_out;

    prep_kernel<<<(56320 + 255)/256, 256>>>(w1a, w1b, w2a, w2b, wa1, wa2, w3a, w3b);

    cudaFuncSetAttribute(value_net_mma,
                         cudaFuncAttributeMaxDynamicSharedMemorySize, SMEM_BYTES);
    value_net_mma<<<4096, TPB, SMEM_BYTES>>>(
        state, b1a, b1b, b2a, b2b, ba1, ba2, wa3, ba3);

    cudaFuncSetAttribute(value_net_tail,
                         cudaFuncAttributeMaxDynamicSharedMemorySize, TSMEM_BYTES);
    value_net_tail<<<64, TPB, TSMEM_BYTES>>>(b3a, b3b, w3c, b3c, out);
}